// round 11
// baseline (speedup 1.0000x reference)
#include <cuda_runtime.h>
#include <cstddef>
#include <cstdint>

// ---------------------------------------------------------------------------
// Problem constants
// ---------------------------------------------------------------------------
#define BSZ   4096
#define NALLY 31
#define NEN   32
#define D_OWN 128
#define D_AL  64
#define D_EN  65
#define ADIM  128
#define EDIM  256
#define HDIM  512
#define NACT  6
#define QOUT  (NACT + NEN)   // 38
#define M_AQ  (NEN * BSZ)    // 131072

#define KP_E   40     // enemy packed kpairs (K=80, zero-padded from 65)
#define KP_X   192    // X packed kpairs (K=384: 128 own | 128 ally-seg | 128 enemy-seg)
#define KP_H   256    // K=512
#define XCOLS  384

#define SM256_BYTES 73728   // dynamic smem for 256-tile kernels (A 48KB + B 24KB)

// ---------------------------------------------------------------------------
// Scratch (static device globals; no runtime allocation)
// ---------------------------------------------------------------------------
__device__ float g_X      [BSZ * XCOLS];
__device__ float g_qaqe   [BSZ * 256];
__device__ float g_gi     [BSZ * 3 * HDIM];
__device__ float g_gh     [BSZ * 3 * HDIM];
__device__ float g_hterm  [BSZ * HDIM];
__device__ float g_cvec   [HDIM];
__device__ float g_We1T   [HDIM * D_EN];
__device__ float g_Wa1topT[HDIM * HDIM];
__device__ float g_Wa1botT[HDIM * HDIM];
__device__ float g_Bq     [256 * ADIM];
__device__ float g_bqaqe  [256];
__device__ float g_biasgi [3 * HDIM];
// packed (hi/lo bf16x2 per kpair)
__device__ uint2 g_Ep     [(size_t)M_AQ * KP_E];
__device__ uint2 g_We1Tp  [HDIM * KP_E];
__device__ uint2 g_We2p   [HDIM * KP_H];
__device__ uint2 g_Wa1topTp[HDIM * KP_H];
__device__ uint2 g_Mtp    [HDIM * KP_H];
__device__ uint2 g_Wa1botTp[HDIM * KP_H];
__device__ uint2 g_wihp   [3][3 * HDIM * 128];
__device__ uint2 g_Wovp   [128 * 128];
__device__ uint2 g_Wavp   [128 * 128];
__device__ uint2 g_Wevp   [128 * 128];
__device__ uint2 g_Wgip   [3 * HDIM * KP_X];
__device__ uint2 g_whhp   [3 * HDIM * KP_H];
__device__ uint2 g_Bqp    [256 * 64];
__device__ uint2 g_ownp   [BSZ * 64];
__device__ uint2 g_Xp     [BSZ * KP_X];
__device__ uint2 g_hidp   [BSZ * KP_H];
__device__ uint2 g_hp     [BSZ * KP_H];
__device__ uint2 g_relu1p [(size_t)M_AQ * KP_H];    // 268 MB

// ---------------------------------------------------------------------------
// bf16 split helpers
// ---------------------------------------------------------------------------
__device__ __forceinline__ uint2 split_pair(float f0, float f1) {
    uint32_t h;
    asm("cvt.rn.bf16x2.f32 %0, %1, %2;" : "=r"(h) : "f"(f1), "f"(f0));  // lo16=f0, hi16=f1
    float h0 = __uint_as_float(h << 16);
    float h1 = __uint_as_float(h & 0xffff0000u);
    uint32_t l;
    asm("cvt.rn.bf16x2.f32 %0, %1, %2;" : "=r"(l) : "f"(f1 - h1), "f"(f0 - h0));
    return make_uint2(h, l);
}

__device__ __forceinline__ void mma_bf16(float* c, const uint32_t* a,
                                         uint32_t b0, uint32_t b1) {
    asm volatile(
        "mma.sync.aligned.m16n8k16.row.col.f32.bf16.bf16.f32 "
        "{%0,%1,%2,%3}, {%4,%5,%6,%7}, {%8,%9}, {%0,%1,%2,%3};"
        : "+f"(c[0]), "+f"(c[1]), "+f"(c[2]), "+f"(c[3])
        : "r"(a[0]), "r"(a[1]), "r"(a[2]), "r"(a[3]), "r"(b0), "r"(b1));
}

// ---------------------------------------------------------------------------
// 128-tile packed mma GEMM (proven round-8 kernel; used for small-M ops).
// C[m,n] = sum_k A[m,k]*B[n,k]. PACKOUT=1: uint2 packed out (ldc in kpairs).
// ---------------------------------------------------------------------------
template <int PACKOUT>
__global__ void __launch_bounds__(256)
mma_pk(const uint2* __restrict__ Ap, const uint2* __restrict__ Bp,
       const float* __restrict__ bias, float* __restrict__ C,
       int Kp, int ldap, int ldbp, int ldc, int relu)
{
    __shared__ uint32_t sm[2][2][2][128][12];   // [buf][A/B][hi/lo][row][kpair+pad]

    const int tid = threadIdx.x;
    const int lane = tid & 31, wid = tid >> 5;
    const int warpM = wid & 3, warpN = wid >> 2;
    const int gid = lane >> 2, tg = lane & 3;
    const int rowBase = blockIdx.y * 128;
    const int colBase = blockIdx.x * 128;

    float acc[2][8][4];
#pragma unroll
    for (int mt = 0; mt < 2; mt++)
#pragma unroll
        for (int nt = 0; nt < 8; nt++)
#pragma unroll
            for (int i = 0; i < 4; i++) acc[mt][nt][i] = 0.f;

    const int nSlices = Kp >> 3;
    const int r = tid >> 1;
    const int ph = (tid & 1) * 4;
    const uint2* aRow = Ap + (size_t)(rowBase + r) * ldap + ph;
    const uint2* bRow = Bp + (size_t)(colBase + r) * ldbp + ph;

    uint4 ua0, ua1, ub0, ub1;
    auto ldg_slice = [&](int k0p) {
        ua0 = *(const uint4*)(aRow + k0p);
        ua1 = *(const uint4*)(aRow + k0p + 2);
        ub0 = *(const uint4*)(bRow + k0p);
        ub1 = *(const uint4*)(bRow + k0p + 2);
    };
    auto sts_slice = [&](int buf) {
        sm[buf][0][0][r][ph+0] = ua0.x; sm[buf][0][1][r][ph+0] = ua0.y;
        sm[buf][0][0][r][ph+1] = ua0.z; sm[buf][0][1][r][ph+1] = ua0.w;
        sm[buf][0][0][r][ph+2] = ua1.x; sm[buf][0][1][r][ph+2] = ua1.y;
        sm[buf][0][0][r][ph+3] = ua1.z; sm[buf][0][1][r][ph+3] = ua1.w;
        sm[buf][1][0][r][ph+0] = ub0.x; sm[buf][1][1][r][ph+0] = ub0.y;
        sm[buf][1][0][r][ph+1] = ub0.z; sm[buf][1][1][r][ph+1] = ub0.w;
        sm[buf][1][0][r][ph+2] = ub1.x; sm[buf][1][1][r][ph+2] = ub1.y;
        sm[buf][1][0][r][ph+3] = ub1.z; sm[buf][1][1][r][ph+3] = ub1.w;
    };
    auto compute = [&](int buf) {
        uint32_t ah[2][4], al[2][4];
#pragma unroll
        for (int mt = 0; mt < 2; mt++) {
            int m = warpM * 32 + mt * 16 + gid;
            ah[mt][0] = sm[buf][0][0][m][tg];         al[mt][0] = sm[buf][0][1][m][tg];
            ah[mt][1] = sm[buf][0][0][m + 8][tg];     al[mt][1] = sm[buf][0][1][m + 8][tg];
            ah[mt][2] = sm[buf][0][0][m][tg + 4];     al[mt][2] = sm[buf][0][1][m][tg + 4];
            ah[mt][3] = sm[buf][0][0][m + 8][tg + 4]; al[mt][3] = sm[buf][0][1][m + 8][tg + 4];
        }
#pragma unroll
        for (int nt = 0; nt < 8; nt++) {
            int n = warpN * 64 + nt * 8 + gid;
            uint32_t bh0 = sm[buf][1][0][n][tg], bh1 = sm[buf][1][0][n][tg + 4];
            uint32_t bl0 = sm[buf][1][1][n][tg], bl1 = sm[buf][1][1][n][tg + 4];
#pragma unroll
            for (int mt = 0; mt < 2; mt++) {
                mma_bf16(acc[mt][nt], ah[mt], bh0, bh1);
                mma_bf16(acc[mt][nt], ah[mt], bl0, bl1);
                mma_bf16(acc[mt][nt], al[mt], bh0, bh1);
            }
        }
    };

    ldg_slice(0);
    for (int kc = 0; kc < nSlices; kc++) {
        sts_slice(kc & 1);
        if (kc + 1 < nSlices) ldg_slice((kc + 1) * 8);
        __syncthreads();
        compute(kc & 1);
    }

#pragma unroll
    for (int mt = 0; mt < 2; mt++) {
        int r0 = rowBase + warpM * 32 + mt * 16 + gid;
#pragma unroll
        for (int nt = 0; nt < 8; nt++) {
            int cc = colBase + warpN * 64 + nt * 8 + 2 * tg;
            float b0v = bias ? __ldg(bias + cc) : 0.f;
            float b1v = bias ? __ldg(bias + cc + 1) : 0.f;
            float v0 = acc[mt][nt][0] + b0v, v1 = acc[mt][nt][1] + b1v;
            float v2 = acc[mt][nt][2] + b0v, v3 = acc[mt][nt][3] + b1v;
            if (relu) {
                v0 = fmaxf(v0, 0.f); v1 = fmaxf(v1, 0.f);
                v2 = fmaxf(v2, 0.f); v3 = fmaxf(v3, 0.f);
            }
            if (PACKOUT) {
                uint2* Cp = (uint2*)C;
                Cp[(size_t)r0 * ldc + (cc >> 1)] = split_pair(v0, v1);
                Cp[(size_t)(r0 + 8) * ldc + (cc >> 1)] = split_pair(v2, v3);
            } else {
                *(float2*)&C[(size_t)r0 * ldc + cc] = make_float2(v0, v1);
                *(float2*)&C[(size_t)(r0 + 8) * ldc + cc] = make_float2(v2, v3);
            }
        }
    }
}

// ---------------------------------------------------------------------------
// 256-tile packed mma GEMM: BM=256, BN=128, 8 warps (4m x 2n), warp tile
// 64x64 (mt=4). 1.5x less smem traffic per HMMA than the 128-tile kernel.
// Dynamic smem 72KB: A planes [2buf][2pl][256][12], then B [2][2][128][12].
// ---------------------------------------------------------------------------
#define SA_IDX(buf, pl, row, kp) ((((buf) * 2 + (pl)) * 256 + (row)) * 12 + (kp))
#define SB_IDX(buf, pl, row, kp) (12288 + (((buf) * 2 + (pl)) * 128 + (row)) * 12 + (kp))

template <int PACKOUT>
__global__ void __launch_bounds__(256)
mma_pk256(const uint2* __restrict__ Ap, const uint2* __restrict__ Bp,
          const float* __restrict__ bias, float* __restrict__ C,
          int Kp, int ldap, int ldbp, int ldc, int relu)
{
    extern __shared__ uint32_t sm[];

    const int tid = threadIdx.x;
    const int lane = tid & 31, wid = tid >> 5;
    const int warpM = wid & 3, warpN = wid >> 2;
    const int gid = lane >> 2, tg = lane & 3;
    const int rowBase = blockIdx.y * 256;
    const int colBase = blockIdx.x * 128;

    float acc[4][8][4];
#pragma unroll
    for (int mt = 0; mt < 4; mt++)
#pragma unroll
        for (int nt = 0; nt < 8; nt++)
#pragma unroll
            for (int i = 0; i < 4; i++) acc[mt][nt][i] = 0.f;

    const int nSlices = Kp >> 3;
    const uint2* aRow = Ap + (size_t)(rowBase + tid) * ldap;
    const int rb = tid & 127, cb = (tid >> 7) * 4;
    const uint2* bRow = Bp + (size_t)(colBase + rb) * ldbp + cb;

    uint4 a0, a1, a2, a3, b0, b1;
    auto ldg_slice = [&](int k0p) {
        a0 = *(const uint4*)(aRow + k0p);
        a1 = *(const uint4*)(aRow + k0p + 2);
        a2 = *(const uint4*)(aRow + k0p + 4);
        a3 = *(const uint4*)(aRow + k0p + 6);
        b0 = *(const uint4*)(bRow + k0p);
        b1 = *(const uint4*)(bRow + k0p + 2);
    };
    auto sts_slice = [&](int buf) {
        sm[SA_IDX(buf,0,tid,0)] = a0.x; sm[SA_IDX(buf,1,tid,0)] = a0.y;
        sm[SA_IDX(buf,0,tid,1)] = a0.z; sm[SA_IDX(buf,1,tid,1)] = a0.w;
        sm[SA_IDX(buf,0,tid,2)] = a1.x; sm[SA_IDX(buf,1,tid,2)] = a1.y;
        sm[SA_IDX(buf,0,tid,3)] = a1.z; sm[SA_IDX(buf,1,tid,3)] = a1.w;
        sm[SA_IDX(buf,0,tid,4)] = a2.x; sm[SA_IDX(buf,1,tid,4)] = a2.y;
        sm[SA_IDX(buf,0,tid,5)] = a2.z; sm[SA_IDX(buf,1,tid,5)] = a2.w;
        sm[SA_IDX(buf,0,tid,6)] = a3.x; sm[SA_IDX(buf,1,tid,6)] = a3.y;
        sm[SA_IDX(buf,0,tid,7)] = a3.z; sm[SA_IDX(buf,1,tid,7)] = a3.w;
        sm[SB_IDX(buf,0,rb,cb+0)] = b0.x; sm[SB_IDX(buf,1,rb,cb+0)] = b0.y;
        sm[SB_IDX(buf,0,rb,cb+1)] = b0.z; sm[SB_IDX(buf,1,rb,cb+1)] = b0.w;
        sm[SB_IDX(buf,0,rb,cb+2)] = b1.x; sm[SB_IDX(buf,1,rb,cb+2)] = b1.y;
        sm[SB_IDX(buf,0,rb,cb+3)] = b1.z; sm[SB_IDX(buf,1,rb,cb+3)] = b1.w;
    };
    auto compute = [&](int buf) {
        uint32_t ah[4][4], al[4][4];
#pragma unroll
        for (int mt = 0; mt < 4; mt++) {
            int m = warpM * 64 + mt * 16 + gid;
            ah[mt][0] = sm[SA_IDX(buf,0,m,tg)];     al[mt][0] = sm[SA_IDX(buf,1,m,tg)];
            ah[mt][1] = sm[SA_IDX(buf,0,m+8,tg)];   al[mt][1] = sm[SA_IDX(buf,1,m+8,tg)];
            ah[mt][2] = sm[SA_IDX(buf,0,m,tg+4)];   al[mt][2] = sm[SA_IDX(buf,1,m,tg+4)];
            ah[mt][3] = sm[SA_IDX(buf,0,m+8,tg+4)]; al[mt][3] = sm[SA_IDX(buf,1,m+8,tg+4)];
        }
#pragma unroll
        for (int nt = 0; nt < 8; nt++) {
            int n = warpN * 64 + nt * 8 + gid;
            uint32_t bh0 = sm[SB_IDX(buf,0,n,tg)], bh1 = sm[SB_IDX(buf,0,n,tg+4)];
            uint32_t bl0 = sm[SB_IDX(buf,1,n,tg)], bl1 = sm[SB_IDX(buf,1,n,tg+4)];
#pragma unroll
            for (int mt = 0; mt < 4; mt++) {
                mma_bf16(acc[mt][nt], ah[mt], bh0, bh1);
                mma_bf16(acc[mt][nt], ah[mt], bl0, bl1);
                mma_bf16(acc[mt][nt], al[mt], bh0, bh1);
            }
        }
    };

    ldg_slice(0);
    for (int kc = 0; kc < nSlices; kc++) {
        sts_slice(kc & 1);
        if (kc + 1 < nSlices) ldg_slice((kc + 1) * 8);
        __syncthreads();
        compute(kc & 1);
    }

#pragma unroll
    for (int mt = 0; mt < 4; mt++) {
        int r0 = rowBase + warpM * 64 + mt * 16 + gid;
#pragma unroll
        for (int nt = 0; nt < 8; nt++) {
            int cc = colBase + warpN * 64 + nt * 8 + 2 * tg;
            float b0v = bias ? __ldg(bias + cc) : 0.f;
            float b1v = bias ? __ldg(bias + cc + 1) : 0.f;
            float v0 = acc[mt][nt][0] + b0v, v1 = acc[mt][nt][1] + b1v;
            float v2 = acc[mt][nt][2] + b0v, v3 = acc[mt][nt][3] + b1v;
            if (relu) {
                v0 = fmaxf(v0, 0.f); v1 = fmaxf(v1, 0.f);
                v2 = fmaxf(v2, 0.f); v3 = fmaxf(v3, 0.f);
            }
            if (PACKOUT) {
                uint2* Cp = (uint2*)C;
                Cp[(size_t)r0 * ldc + (cc >> 1)] = split_pair(v0, v1);
                Cp[(size_t)(r0 + 8) * ldc + (cc >> 1)] = split_pair(v2, v3);
            } else {
                *(float2*)&C[(size_t)r0 * ldc + cc] = make_float2(v0, v1);
                *(float2*)&C[(size_t)(r0 + 8) * ldc + cc] = make_float2(v2, v3);
            }
        }
    }
}

// ---------------------------------------------------------------------------
// aq 256-tile kernel with in-kernel column-chunk loop: grid (1, 512).
// Keeps aq partials in registers across 4 column chunks (relu1p re-read hits
// L2), then smem cross-warp reduce + direct out write. No atomics/aqpart.
// ---------------------------------------------------------------------------
__global__ void __launch_bounds__(256)
mma_aq256(const uint2* __restrict__ Ap, const uint2* __restrict__ Bp,
          const float* __restrict__ hterm, const float* __restrict__ Wa2,
          const float* __restrict__ ba2, float* __restrict__ out)
{
    extern __shared__ uint32_t sm[];

    const int tid = threadIdx.x;
    const int lane = tid & 31, wid = tid >> 5;
    const int warpM = wid & 3, warpN = wid >> 2;
    const int gid = lane >> 2, tg = lane & 3;
    const int rowBase = blockIdx.y * 256;
    const int nSlices = KP_H >> 3;   // 32 (even: no cross-chunk buffer hazard)

    const uint2* aRow = Ap + (size_t)(rowBase + tid) * KP_H;
    const int rb = tid & 127, cb = (tid >> 7) * 4;

    float acc[4][8][4];
#pragma unroll
    for (int mt = 0; mt < 4; mt++)
#pragma unroll
        for (int nt = 0; nt < 8; nt++)
#pragma unroll
            for (int i = 0; i < 4; i++) acc[mt][nt][i] = 0.f;
    float p[4][2] = {{0.f,0.f},{0.f,0.f},{0.f,0.f},{0.f,0.f}};

    for (int ccblk = 0; ccblk < 4; ccblk++) {
        const uint2* bRow = Bp + (size_t)(ccblk * 128 + rb) * KP_H + cb;

        uint4 a0, a1, a2, a3, b0, b1;
        auto ldg_slice = [&](int k0p) {
            a0 = *(const uint4*)(aRow + k0p);
            a1 = *(const uint4*)(aRow + k0p + 2);
            a2 = *(const uint4*)(aRow + k0p + 4);
            a3 = *(const uint4*)(aRow + k0p + 6);
            b0 = *(const uint4*)(bRow + k0p);
            b1 = *(const uint4*)(bRow + k0p + 2);
        };
        auto sts_slice = [&](int buf) {
            sm[SA_IDX(buf,0,tid,0)] = a0.x; sm[SA_IDX(buf,1,tid,0)] = a0.y;
            sm[SA_IDX(buf,0,tid,1)] = a0.z; sm[SA_IDX(buf,1,tid,1)] = a0.w;
            sm[SA_IDX(buf,0,tid,2)] = a1.x; sm[SA_IDX(buf,1,tid,2)] = a1.y;
            sm[SA_IDX(buf,0,tid,3)] = a1.z; sm[SA_IDX(buf,1,tid,3)] = a1.w;
            sm[SA_IDX(buf,0,tid,4)] = a2.x; sm[SA_IDX(buf,1,tid,4)] = a2.y;
            sm[SA_IDX(buf,0,tid,5)] = a2.z; sm[SA_IDX(buf,1,tid,5)] = a2.w;
            sm[SA_IDX(buf,0,tid,6)] = a3.x; sm[SA_IDX(buf,1,tid,6)] = a3.y;
            sm[SA_IDX(buf,0,tid,7)] = a3.z; sm[SA_IDX(buf,1,tid,7)] = a3.w;
            sm[SB_IDX(buf,0,rb,cb+0)] = b0.x; sm[SB_IDX(buf,1,rb,cb+0)] = b0.y;
            sm[SB_IDX(buf,0,rb,cb+1)] = b0.z; sm[SB_IDX(buf,1,rb,cb+1)] = b0.w;
            sm[SB_IDX(buf,0,rb,cb+2)] = b1.x; sm[SB_IDX(buf,1,rb,cb+2)] = b1.y;
            sm[SB_IDX(buf,0,rb,cb+3)] = b1.z; sm[SB_IDX(buf,1,rb,cb+3)] = b1.w;
        };
        auto compute = [&](int buf) {
            uint32_t ah[4][4], al[4][4];
#pragma unroll
            for (int mt = 0; mt < 4; mt++) {
                int m = warpM * 64 + mt * 16 + gid;
                ah[mt][0] = sm[SA_IDX(buf,0,m,tg)];     al[mt][0] = sm[SA_IDX(buf,1,m,tg)];
                ah[mt][1] = sm[SA_IDX(buf,0,m+8,tg)];   al[mt][1] = sm[SA_IDX(buf,1,m+8,tg)];
                ah[mt][2] = sm[SA_IDX(buf,0,m,tg+4)];   al[mt][2] = sm[SA_IDX(buf,1,m,tg+4)];
                ah[mt][3] = sm[SA_IDX(buf,0,m+8,tg+4)]; al[mt][3] = sm[SA_IDX(buf,1,m+8,tg+4)];
            }
#pragma unroll
            for (int nt = 0; nt < 8; nt++) {
                int n = warpN * 64 + nt * 8 + gid;
                uint32_t bh0 = sm[SB_IDX(buf,0,n,tg)], bh1 = sm[SB_IDX(buf,0,n,tg+4)];
                uint32_t bl0 = sm[SB_IDX(buf,1,n,tg)], bl1 = sm[SB_IDX(buf,1,n,tg+4)];
#pragma unroll
                for (int mt = 0; mt < 4; mt++) {
                    mma_bf16(acc[mt][nt], ah[mt], bh0, bh1);
                    mma_bf16(acc[mt][nt], ah[mt], bl0, bl1);
                    mma_bf16(acc[mt][nt], al[mt], bh0, bh1);
                }
            }
        };

        ldg_slice(0);
        for (int kc = 0; kc < nSlices; kc++) {
            sts_slice(kc & 1);
            if (kc + 1 < nSlices) ldg_slice((kc + 1) * 8);
            __syncthreads();
            compute(kc & 1);
        }

        // fold chunk into partials, reset acc
#pragma unroll
        for (int mt = 0; mt < 4; mt++) {
            int r0 = rowBase + warpM * 64 + mt * 16 + gid;
            const float* h0 = hterm + (size_t)(r0 & (BSZ - 1)) * HDIM;
            const float* h1 = hterm + (size_t)((r0 + 8) & (BSZ - 1)) * HDIM;
#pragma unroll
            for (int nt = 0; nt < 8; nt++) {
                int cc = ccblk * 128 + warpN * 64 + nt * 8 + 2 * tg;
                float w0 = __ldg(Wa2 + cc), w1 = __ldg(Wa2 + cc + 1);
                p[mt][0] += fmaxf(acc[mt][nt][0] + __ldg(h0 + cc), 0.f) * w0
                          + fmaxf(acc[mt][nt][1] + __ldg(h0 + cc + 1), 0.f) * w1;
                p[mt][1] += fmaxf(acc[mt][nt][2] + __ldg(h1 + cc), 0.f) * w0
                          + fmaxf(acc[mt][nt][3] + __ldg(h1 + cc + 1), 0.f) * w1;
#pragma unroll
                for (int i = 0; i < 4; i++) acc[mt][nt][i] = 0.f;
            }
        }
    }

    // quad reduce (over tg lanes = column groups)
#pragma unroll
    for (int mt = 0; mt < 4; mt++)
#pragma unroll
        for (int j = 0; j < 2; j++) {
            p[mt][j] += __shfl_xor_sync(0xffffffffu, p[mt][j], 1);
            p[mt][j] += __shfl_xor_sync(0xffffffffu, p[mt][j], 2);
        }

    // cross-warp (warpN) reduce via smem, then direct write
    __syncthreads();
    float* pbuf = (float*)sm;
    pbuf[tid] = 0.f;
    __syncthreads();
    if (tg == 0) {
#pragma unroll
        for (int mt = 0; mt < 4; mt++) {
            int rl = warpM * 64 + mt * 16 + gid;
            atomicAdd(&pbuf[rl], p[mt][0]);
            atomicAdd(&pbuf[rl + 8], p[mt][1]);
        }
    }
    __syncthreads();
    {
        int r0 = rowBase + tid;
        int b = r0 & (BSZ - 1), n = r0 >> 12;
        out[(size_t)b * QOUT + NACT + n] = pbuf[tid] + __ldg(ba2);
    }
}

// ---------------------------------------------------------------------------
// pack: fp32 [R, Csrc] (ld lds) -> packed uint2 [R, ldp], zero-pad k >= Csrc
// ---------------------------------------------------------------------------
__global__ void pack_kernel(const float* __restrict__ src, uint2* __restrict__ dst,
                            int R, int Csrc, int lds, int ldp)
{
    int idx = blockIdx.x * blockDim.x + threadIdx.x;
    if (idx >= R * ldp) return;
    int r = idx / ldp, p = idx - r * ldp;
    int k = 2 * p;
    float f0 = (k < Csrc) ? src[(size_t)r * lds + k] : 0.f;
    float f1 = (k + 1 < Csrc) ? src[(size_t)r * lds + k + 1] : 0.f;
    dst[(size_t)r * ldp + p] = split_pair(f0, f1);
}

// warp-dot GEMM: C[m,n] = sum_k A[m,k]*B[n,k]; one warp per output
__global__ void warpdot_kernel(const float* __restrict__ A, const float* __restrict__ B,
                               float* __restrict__ C, int M, int N, int K,
                               int lda, int ldb, int ldc)
{
    int idx = (blockIdx.x * blockDim.x + threadIdx.x) >> 5;
    int lane = threadIdx.x & 31;
    if (idx >= M * N) return;
    int m = idx / N, n = idx - m * N;
    float s = 0.f;
    for (int k = lane; k < K; k += 32) s += A[(size_t)m * lda + k] * B[(size_t)n * ldb + k];
#pragma unroll
    for (int o = 16; o; o >>= 1) s += __shfl_xor_sync(0xffffffffu, s, o);
    if (lane == 0) C[(size_t)m * ldc + n] = s;
}

// vecrow: out[j] = sum_k v[k] * W[j*ldw + k]   (row-dot), one warp per j
__global__ void vecrow_kernel(const float* __restrict__ v, const float* __restrict__ W,
                              float* __restrict__ out, int K, int N, int ldw)
{
    int j = (blockIdx.x * blockDim.x + threadIdx.x) >> 5;
    int lane = threadIdx.x & 31;
    if (j >= N) return;
    float s = 0.f;
    for (int k = lane; k < K; k += 32) s += v[k] * W[(size_t)j * ldw + k];
#pragma unroll
    for (int o = 16; o; o >>= 1) s += __shfl_xor_sync(0xffffffffu, s, o);
    if (lane == 0) out[j] = s;
}

// vecmat: out[j] = sum_k v[k] * W[k*ldw + j] (+bias[j]); one warp per j
__global__ void vecmat_kernel(const float* __restrict__ v, const float* __restrict__ W,
                              const float* __restrict__ bias, float* __restrict__ out,
                              int K, int N, int ldw)
{
    int j = (blockIdx.x * blockDim.x + threadIdx.x) >> 5;
    int lane = threadIdx.x & 31;
    if (j >= N) return;
    float s = 0.f;
    for (int k = lane; k < K; k += 32) s += v[k] * W[(size_t)k * ldw + j];
#pragma unroll
    for (int o = 16; o; o >>= 1) s += __shfl_xor_sync(0xffffffffu, s, o);
    if (lane == 0) out[j] = s + (bias ? bias[j] : 0.f);
}

// bias_gi[n] = b_ih[n] + bov.wih[n,0:256] + bav.wih[n,256:512] + bev.wih[n,512:768]
__global__ void biasgi_kernel(const float* __restrict__ bov, const float* __restrict__ bav,
                              const float* __restrict__ bev, const float* __restrict__ wih,
                              const float* __restrict__ bih, float* __restrict__ out)
{
    int n = (blockIdx.x * blockDim.x + threadIdx.x) >> 5;
    int lane = threadIdx.x & 31;
    if (n >= 3 * HDIM) return;
    float s = 0.f;
    for (int e = lane; e < 768; e += 32) {
        float c = (e < 256) ? bov[e] : (e < 512) ? bav[e - 256] : bev[e - 512];
        s += c * wih[(size_t)n * 768 + e];
    }
#pragma unroll
    for (int o = 16; o; o >>= 1) s += __shfl_xor_sync(0xffffffffu, s, o);
    if (lane == 0) out[n] = s + bih[n];
}

// naive transpose: out[j, i] = in[i, j]  for in[R, C]
__global__ void transpose_kernel(const float* __restrict__ in, float* __restrict__ out,
                                 int R, int C)
{
    int idx = blockIdx.x * blockDim.x + threadIdx.x;
    if (idx >= R * C) return;
    int i = idx / C, j = idx - i * C;
    out[(size_t)j * R + i] = in[idx];
}

// ---------------------------------------------------------------------------
// Attention: one warp per batch element; qproj has row stride ldq.
// ---------------------------------------------------------------------------
template <int D, int Nn>
__global__ void attn_kernel(const float* __restrict__ feats,   // [Nn, B, D]
                            const float* __restrict__ qproj,   // [B, ldq]
                            int ldq, float* __restrict__ fw, int ldf)
{
    constexpr int NC = (D + 31) / 32;
    const int warp = (blockIdx.x * blockDim.x + threadIdx.x) >> 5;
    const int lane = threadIdx.x & 31;
    if (warp >= BSZ) return;
    const int b = warp;

    float qv[NC];
#pragma unroll
    for (int c = 0; c < NC; c++) {
        int d = lane + c * 32;
        qv[c] = (d < D) ? qproj[(size_t)b * ldq + d] : 0.f;
    }

    const float scale = rsqrtf((float)ADIM);
    float myE = 0.f, m = -1e30f;
    for (int n = 0; n < Nn; n++) {
        const float* f = feats + ((size_t)n * BSZ + b) * D;
        float p = 0.f;
#pragma unroll
        for (int c = 0; c < NC; c++) {
            int d = lane + c * 32;
            if (d < D) p += f[d] * qv[c];
        }
#pragma unroll
        for (int o = 16; o; o >>= 1) p += __shfl_xor_sync(0xffffffffu, p, o);
        p *= scale;
        if (lane == n) myE = p;
        m = fmaxf(m, p);
    }
    float wgt = (lane < Nn) ? expf(myE - m) : 0.f;
    float s = wgt;
#pragma unroll
    for (int o = 16; o; o >>= 1) s += __shfl_xor_sync(0xffffffffu, s, o);
    const float attnW = wgt / s;

    float acc[NC];
#pragma unroll
    for (int c = 0; c < NC; c++) acc[c] = 0.f;
    for (int n = 0; n < Nn; n++) {
        float a = __shfl_sync(0xffffffffu, attnW, n);
        const float* f = feats + ((size_t)n * BSZ + b) * D;
#pragma unroll
        for (int c = 0; c < NC; c++) {
            int d = lane + c * 32;
            if (d < D) acc[c] += a * f[d];
        }
    }
#pragma unroll
    for (int c = 0; c < NC; c++) {
        int d = lane + c * 32;
        if (d < D) fw[(size_t)b * ldf + d] = acc[c];
    }
}

// copy own_obs into X[:, 0:128] (X row stride XCOLS)
__global__ void copyx_kernel(const float* __restrict__ own, float* __restrict__ X)
{
    int idx = blockIdx.x * blockDim.x + threadIdx.x;   // over BSZ*32 float4s
    if (idx >= BSZ * 32) return;
    int b = idx >> 5, j4 = idx & 31;
    *(float4*)&X[(size_t)b * XCOLS + j4 * 4] = *(const float4*)&own[(size_t)b * D_OWN + j4 * 4];
}

// GRU gate fusion
__global__ void gru_gate_kernel(const float* __restrict__ gi, const float* __restrict__ gh,
                                const float* __restrict__ hprev, float* __restrict__ hout)
{
    int idx = blockIdx.x * blockDim.x + threadIdx.x;
    if (idx >= BSZ * HDIM) return;
    int b = idx >> 9, k = idx & (HDIM - 1);
    const float* gib = gi + (size_t)b * 3 * HDIM;
    const float* ghb = gh + (size_t)b * 3 * HDIM;
    float ir = gib[k], iz = gib[HDIM + k], in_ = gib[2 * HDIM + k];
    float hr = ghb[k], hz = ghb[HDIM + k], hn  = ghb[2 * HDIM + k];
    float r = 1.f / (1.f + expf(-(ir + hr)));
    float z = 1.f / (1.f + expf(-(iz + hz)));
    float n = tanhf(in_ + r * hn);
    hout[idx] = (1.f - z) * n + z * hprev[idx];
}

// wo_q head
__global__ void woq_kernel(const float* __restrict__ h, const float* __restrict__ Wwo,
                           const float* __restrict__ bwo, float* __restrict__ out)
{
    int idx = blockIdx.x * blockDim.x + threadIdx.x;
    if (idx >= BSZ * NACT) return;
    int b = idx / NACT, j = idx - b * NACT;
    const float* hb = h + (size_t)b * HDIM;
    float s = bwo[j];
#pragma unroll 8
    for (int k = 0; k < HDIM; k++) s += hb[k] * __ldg(&Wwo[k * NACT + j]);
    out[(size_t)b * QOUT + j] = s;
}

// ---------------------------------------------------------------------------
// Host launcher
// ---------------------------------------------------------------------------
extern "C" void kernel_launch(void* const* d_in, const int* in_sizes, int n_in,
                              void* d_out, int out_size)
{
    (void)in_sizes; (void)n_in; (void)out_size;
    const float* own_obs = (const float*)d_in[0];
    const float* ally    = (const float*)d_in[1];
    const float* enemy   = (const float*)d_in[2];
    const float* hidden  = (const float*)d_in[3];
    const float* Wq   = (const float*)d_in[4];
    const float* bq   = (const float*)d_in[5];
    const float* Wak  = (const float*)d_in[6];
    const float* Wav  = (const float*)d_in[8];
    const float* bav  = (const float*)d_in[9];
    const float* Wek  = (const float*)d_in[10];
    const float* Wev  = (const float*)d_in[12];
    const float* bev  = (const float*)d_in[13];
    const float* Wov  = (const float*)d_in[14];
    const float* bov  = (const float*)d_in[15];
    const float* w_ih = (const float*)d_in[16];
    const float* w_hh = (const float*)d_in[17];
    const float* b_ih = (const float*)d_in[18];
    const float* b_hh = (const float*)d_in[19];
    const float* Wwo  = (const float*)d_in[20];
    const float* bwo  = (const float*)d_in[21];
    const float* We1  = (const float*)d_in[22];
    const float* be1  = (const float*)d_in[23];
    const float* We2  = (const float*)d_in[24];
    const float* be2  = (const float*)d_in[25];
    const float* Wa1  = (const float*)d_in[26];
    const float* ba1  = (const float*)d_in[27];
    const float* Wa2  = (const float*)d_in[28];
    const float* ba2  = (const float*)d_in[29];

    float* out   = (float*)d_out;
    float* h_out = out + (size_t)BSZ * QOUT;

    float *p_X, *p_qaqe, *p_gi, *p_gh, *p_hterm, *p_cvec, *p_We1T;
    float *p_Wa1topT, *p_Wa1botT, *p_Bq, *p_bqaqe, *p_biasgi;
    uint2 *p_Ep, *p_We1Tp, *p_We2p, *p_Wa1topTp, *p_Mtp, *p_Wa1botTp;
    uint2 *p_wihp, *p_Wovp, *p_Wavp, *p_Wevp, *p_Wgip, *p_whhp;
    uint2 *p_Bqp, *p_ownp, *p_Xp, *p_hidp, *p_hp, *p_relu1p;
    cudaGetSymbolAddress((void**)&p_X, g_X);
    cudaGetSymbolAddress((void**)&p_qaqe, g_qaqe);
    cudaGetSymbolAddress((void**)&p_gi, g_gi);
    cudaGetSymbolAddress((void**)&p_gh, g_gh);
    cudaGetSymbolAddress((void**)&p_hterm, g_hterm);
    cudaGetSymbolAddress((void**)&p_cvec, g_cvec);
    cudaGetSymbolAddress((void**)&p_We1T, g_We1T);
    cudaGetSymbolAddress((void**)&p_Wa1topT, g_Wa1topT);
    cudaGetSymbolAddress((void**)&p_Wa1botT, g_Wa1botT);
    cudaGetSymbolAddress((void**)&p_Bq, g_Bq);
    cudaGetSymbolAddress((void**)&p_bqaqe, g_bqaqe);
    cudaGetSymbolAddress((void**)&p_biasgi, g_biasgi);
    cudaGetSymbolAddress((void**)&p_Ep, g_Ep);
    cudaGetSymbolAddress((void**)&p_We1Tp, g_We1Tp);
    cudaGetSymbolAddress((void**)&p_We2p, g_We2p);
    cudaGetSymbolAddress((void**)&p_Wa1topTp, g_Wa1topTp);
    cudaGetSymbolAddress((void**)&p_Mtp, g_Mtp);
    cudaGetSymbolAddress((void**)&p_Wa1botTp, g_Wa1botTp);
    cudaGetSymbolAddress((void**)&p_wihp, g_wihp);
    cudaGetSymbolAddress((void**)&p_Wovp, g_Wovp);
    cudaGetSymbolAddress((void**)&p_Wavp, g_Wavp);
    cudaGetSymbolAddress((void**)&p_Wevp, g_Wevp);
    cudaGetSymbolAddress((void**)&p_Wgip, g_Wgip);
    cudaGetSymbolAddress((void**)&p_whhp, g_whhp);
    cudaGetSymbolAddress((void**)&p_Bqp, g_Bqp);
    cudaGetSymbolAddress((void**)&p_ownp, g_ownp);
    cudaGetSymbolAddress((void**)&p_Xp, g_Xp);
    cudaGetSymbolAddress((void**)&p_hidp, g_hidp);
    cudaGetSymbolAddress((void**)&p_hp, g_hp);
    cudaGetSymbolAddress((void**)&p_relu1p, g_relu1p);

    const int T = 256;
    auto blks = [](long n) { return (int)((n + 255) / 256); };

    cudaFuncSetAttribute(mma_pk256<0>, cudaFuncAttributeMaxDynamicSharedMemorySize, SM256_BYTES);
    cudaFuncSetAttribute(mma_pk256<1>, cudaFuncAttributeMaxDynamicSharedMemorySize, SM256_BYTES);
    cudaFuncSetAttribute(mma_aq256,    cudaFuncAttributeMaxDynamicSharedMemorySize, SM256_BYTES);

    // ---- prep: relu1 dependencies first ----
    pack_kernel<<<blks((long)M_AQ * KP_E), T>>>(enemy, p_Ep, M_AQ, D_EN, D_EN, KP_E);
    transpose_kernel<<<blks(65 * 512), T>>>(We1, p_We1T, 65, 512);
    pack_kernel<<<blks(512 * KP_E), T>>>(p_We1T, p_We1Tp, 512, D_EN, D_EN, KP_E);
    mma_pk256<1><<<dim3(4, 512), 256, SM256_BYTES>>>(p_Ep, p_We1Tp, be1, (float*)p_relu1p,
                                                     KP_E, KP_E, KP_E, KP_H, 1);

    // ---- Mt (packed, tensor-core) ----
    transpose_kernel<<<blks(512 * 512), T>>>(Wa1, p_Wa1topT, 512, 512);
    pack_kernel<<<blks(512 * KP_H), T>>>(p_Wa1topT, p_Wa1topTp, 512, 512, 512, KP_H);
    pack_kernel<<<blks(512 * KP_H), T>>>(We2, p_We2p, 512, 512, 512, KP_H);
    mma_pk<1><<<dim3(4, 4), 256>>>(p_Wa1topTp, p_We2p, nullptr, (float*)p_Mtp,
                                   KP_H, KP_H, KP_H, KP_H, 0);

    // ---- Wa1bot ----
    transpose_kernel<<<blks(512 * 512), T>>>(Wa1 + (size_t)HDIM * HDIM, p_Wa1botT, 512, 512);
    pack_kernel<<<blks(512 * KP_H), T>>>(p_Wa1botT, p_Wa1botTp, 512, 512, 512, KP_H);

    // ---- Wgi folds ----
    pack_kernel<<<blks((long)1536 * 128), T>>>(w_ih,       p_wihp,              1536, 256, 768, 128);
    pack_kernel<<<blks((long)1536 * 128), T>>>(w_ih + 256, p_wihp + 1536*128,   1536, 256, 768, 128);
    pack_kernel<<<blks((long)1536 * 128), T>>>(w_ih + 512, p_wihp + 2*1536*128, 1536, 256, 768, 128);
    pack_kernel<<<blks(128 * 128), T>>>(Wov, p_Wovp, 128, 256, 256, 128);
    cudaMemsetAsync(p_Wavp, 0, 128 * 128 * sizeof(uint2), 0);
    cudaMemsetAsync(p_Wevp, 0, 128 * 128 * sizeof(uint2), 0);
    pack_kernel<<<blks(64 * 128), T>>>(Wav, p_Wavp, 64, 256, 256, 128);
    pack_kernel<<<blks(65 * 128), T>>>(Wev, p_Wevp, 65, 256, 256, 128);
    mma_pk<1><<<dim3(1, 12), 256>>>(p_wihp,              p_Wovp, nullptr, (float*)p_Wgip,
                                    128, 128, 128, KP_X, 0);
    mma_pk<1><<<dim3(1, 12), 256>>>(p_wihp + 1536*128,   p_Wavp, nullptr, (float*)(p_Wgip + 64),
                                    128, 128, 128, KP_X, 0);
    mma_pk<1><<<dim3(1, 12), 256>>>(p_wihp + 2*1536*128, p_Wevp, nullptr, (float*)(p_Wgip + 128),
                                    128, 128, 128, KP_X, 0);
    biasgi_kernel<<<blks(1536 * 32), T>>>(bov, bav, bev, w_ih, b_ih, p_biasgi);

    // ---- folded query head ----
    cudaMemsetAsync(p_Bq, 0, 256 * ADIM * sizeof(float), 0);
    cudaMemsetAsync(p_bqaqe, 0, 256 * sizeof(float), 0);
    warpdot_kernel<<<blks((long)64 * 128 * 32), T>>>(Wak, Wq, p_Bq, 64, 128, 128, 128, 128, 128);
    warpdot_kernel<<<blks((long)65 * 128 * 32), T>>>(Wek, Wq, p_Bq + 64 * 128, 65, 128, 128, 128, 128, 128);
    vecrow_kernel<<<blks(64 * 32), T>>>(bq, Wak, p_bqaqe, 128, 64, 128);
    vecrow_kernel<<<blks(65 * 32), T>>>(bq, Wek, p_bqaqe + 64, 128, 65, 128);
    pack_kernel<<<blks(256 * 64), T>>>(p_Bq, p_Bqp, 256, 128, 128, 64);

    vecmat_kernel<<<blks(512 * 32), T>>>(be2, Wa1, ba1, p_cvec, 512, 512, 512);
    pack_kernel<<<blks((long)1536 * KP_H), T>>>(w_hh, p_whhp, 1536, 512, 512, KP_H);

    // ---- batch path ----
    pack_kernel<<<blks((long)BSZ * 64), T>>>(own_obs, p_ownp, BSZ, 128, 128, 64);
    mma_pk<0><<<dim3(2, 32), 256>>>(p_ownp, p_Bqp, p_bqaqe, p_qaqe, 64, 64, 64, 256, 0);
    cudaMemsetAsync(p_X, 0, (size_t)BSZ * XCOLS * sizeof(float), 0);
    copyx_kernel<<<blks(BSZ * 32), T>>>(own_obs, p_X);
    attn_kernel<D_AL, NALLY><<<BSZ / 8, T>>>(ally, p_qaqe, 256, p_X + 128, XCOLS);
    attn_kernel<D_EN, NEN><<<BSZ / 8, T>>>(enemy, p_qaqe + 64, 256, p_X + 256, XCOLS);
    pack_kernel<<<blks((long)BSZ * KP_X), T>>>(p_X, p_Xp, BSZ, XCOLS, XCOLS, KP_X);
    pack_kernel<<<blks((long)BSZ * KP_H), T>>>(hidden, p_hidp, BSZ, 512, 512, KP_H);

    // GRU (256-row tiles)
    mma_pk256<0><<<dim3(12, 16), 256, SM256_BYTES>>>(p_Xp, p_Wgip, p_biasgi, p_gi,
                                                     KP_X, KP_X, KP_X, 3 * HDIM, 0);
    mma_pk256<0><<<dim3(12, 16), 256, SM256_BYTES>>>(p_hidp, p_whhp, b_hh, p_gh,
                                                     KP_H, KP_H, KP_H, 3 * HDIM, 0);
    gru_gate_kernel<<<blks(BSZ * HDIM), T>>>(p_gi, p_gh, hidden, h_out);
    pack_kernel<<<blks((long)BSZ * KP_H), T>>>(h_out, p_hp, BSZ, 512, 512, KP_H);

    // heads
    woq_kernel<<<blks(BSZ * NACT), T>>>(h_out, Wwo, bwo, out);
    mma_pk<0><<<dim3(4, 32), 256>>>(p_hp, p_Wa1botTp, p_cvec, p_hterm,
                                    KP_H, KP_H, KP_H, HDIM, 0);
    // aq: fused col-chunk loop, direct output (no atomics, no aqpart)
    mma_aq256<<<dim3(1, 512), 256, SM256_BYTES>>>(p_relu1p, p_Mtp, p_hterm, Wa2, ba2, out);
}

// round 12
// speedup vs baseline: 1.0923x; 1.0923x over previous
#include <cuda_runtime.h>
#include <cstddef>
#include <cstdint>

// ---------------------------------------------------------------------------
// Problem constants
// ---------------------------------------------------------------------------
#define BSZ   4096
#define NALLY 31
#define NEN   32
#define D_OWN 128
#define D_AL  64
#define D_EN  65
#define ADIM  128
#define EDIM  256
#define HDIM  512
#define NACT  6
#define QOUT  (NACT + NEN)   // 38
#define M_AQ  (NEN * BSZ)    // 131072

#define KP_E   40     // enemy packed kpairs (K=80, zero-padded from 65)
#define KP_X   192    // X packed kpairs (K=384: 128 own | 128 ally-seg | 128 enemy-seg)
#define KP_H   256    // K=512
#define XCOLS  384

// ---------------------------------------------------------------------------
// Scratch (static device globals; no runtime allocation)
// ---------------------------------------------------------------------------
__device__ float g_X      [BSZ * XCOLS];
__device__ float g_qaqe   [BSZ * 256];
__device__ float g_gi     [BSZ * 3 * HDIM];
__device__ float g_gh     [BSZ * 3 * HDIM];
__device__ float g_hterm  [BSZ * HDIM];
__device__ float g_cvec   [HDIM];
__device__ float g_We1T   [HDIM * D_EN];
__device__ float g_Wa1topT[HDIM * HDIM];
__device__ float g_Wa1botT[HDIM * HDIM];
__device__ float g_Bq     [256 * ADIM];
__device__ float g_bqaqe  [256];
__device__ float g_biasgi [3 * HDIM];
__device__ float g_aqpart [M_AQ];
// packed (hi/lo bf16x2 per kpair)
__device__ uint2 g_Ep     [(size_t)M_AQ * KP_E];
__device__ uint2 g_We1Tp  [HDIM * KP_E];
__device__ uint2 g_We2p   [HDIM * KP_H];
__device__ uint2 g_Wa1topTp[HDIM * KP_H];
__device__ uint2 g_Mtp    [HDIM * KP_H];
__device__ uint2 g_Wa1botTp[HDIM * KP_H];
__device__ uint2 g_wihp   [3][3 * HDIM * 128];
__device__ uint2 g_Wovp   [128 * 128];
__device__ uint2 g_Wavp   [128 * 128];
__device__ uint2 g_Wevp   [128 * 128];
__device__ uint2 g_Wgip   [3 * HDIM * KP_X];
__device__ uint2 g_whhp   [3 * HDIM * KP_H];
__device__ uint2 g_Bqp    [256 * 64];
__device__ uint2 g_ownp   [BSZ * 64];
__device__ uint2 g_Xp     [BSZ * KP_X];
__device__ uint2 g_hidp   [BSZ * KP_H];
__device__ uint2 g_hp     [BSZ * KP_H];
__device__ uint2 g_relu1p [(size_t)M_AQ * KP_H];    // 268 MB

// ---------------------------------------------------------------------------
// bf16 split helpers
// ---------------------------------------------------------------------------
__device__ __forceinline__ uint2 split_pair(float f0, float f1) {
    uint32_t h;
    asm("cvt.rn.bf16x2.f32 %0, %1, %2;" : "=r"(h) : "f"(f1), "f"(f0));  // lo16=f0, hi16=f1
    float h0 = __uint_as_float(h << 16);
    float h1 = __uint_as_float(h & 0xffff0000u);
    uint32_t l;
    asm("cvt.rn.bf16x2.f32 %0, %1, %2;" : "=r"(l) : "f"(f1 - h1), "f"(f0 - h0));
    return make_uint2(h, l);
}

__device__ __forceinline__ void mma_bf16(float* c, const uint32_t* a,
                                         uint32_t b0, uint32_t b1) {
    asm volatile(
        "mma.sync.aligned.m16n8k16.row.col.f32.bf16.bf16.f32 "
        "{%0,%1,%2,%3}, {%4,%5,%6,%7}, {%8,%9}, {%0,%1,%2,%3};"
        : "+f"(c[0]), "+f"(c[1]), "+f"(c[2]), "+f"(c[3])
        : "r"(a[0]), "r"(a[1]), "r"(a[2]), "r"(a[3]), "r"(b0), "r"(b1));
}

// ---------------------------------------------------------------------------
// Packed-input mma GEMM (round-8 proven kernel), now __launch_bounds__(256,2)
// to cap regs at 128 -> 2 CTAs/SM (was 132 regs, 1 CTA/SM, issue 22%).
//   acc += a_hi*b_hi + a_hi*b_lo + a_lo*b_hi  (3-term bf16 split, ~fp32)
//   C[m,n] = sum_k A[m,k]*B[n,k] (+bias[n]) (+relu)
// PACKOUT=1: C is uint2* packed output (ldc in kpairs).
// AQ=1: fused epilogue p[row] += relu(c + hterm[row%B, col]) * Wa2[col],
//       quad-reduced + atomicAdd into C (= aqpart, pre-zeroed).
// ---------------------------------------------------------------------------
template <int AQ, int PACKOUT>
__global__ void __launch_bounds__(256, 2)
mma_pk(const uint2* __restrict__ Ap, const uint2* __restrict__ Bp,
       const float* __restrict__ bias, float* __restrict__ C,
       const float* __restrict__ hterm, const float* __restrict__ Wa2,
       int Kp, int ldap, int ldbp, int ldc, int relu)
{
    __shared__ uint32_t sm[2][2][2][128][12];   // 48KB: [buf][A/B][hi/lo][row][kpair+pad]

    const int tid = threadIdx.x;
    const int lane = tid & 31, wid = tid >> 5;
    const int warpM = wid & 3, warpN = wid >> 2;
    const int gid = lane >> 2, tg = lane & 3;
    const int rowBase = blockIdx.y * 128;
    const int colBase = blockIdx.x * 128;

    float acc[2][8][4];
#pragma unroll
    for (int mt = 0; mt < 2; mt++)
#pragma unroll
        for (int nt = 0; nt < 8; nt++)
#pragma unroll
            for (int i = 0; i < 4; i++) acc[mt][nt][i] = 0.f;

    const int nSlices = Kp >> 3;
    const int r = tid >> 1;
    const int ph = (tid & 1) * 4;
    const uint2* aRow = Ap + (size_t)(rowBase + r) * ldap + ph;
    const uint2* bRow = Bp + (size_t)(colBase + r) * ldbp + ph;

    uint4 ua0, ua1, ub0, ub1;
    auto ldg_slice = [&](int k0p) {
        ua0 = *(const uint4*)(aRow + k0p);
        ua1 = *(const uint4*)(aRow + k0p + 2);
        ub0 = *(const uint4*)(bRow + k0p);
        ub1 = *(const uint4*)(bRow + k0p + 2);
    };
    auto sts_slice = [&](int buf) {
        sm[buf][0][0][r][ph+0] = ua0.x; sm[buf][0][1][r][ph+0] = ua0.y;
        sm[buf][0][0][r][ph+1] = ua0.z; sm[buf][0][1][r][ph+1] = ua0.w;
        sm[buf][0][0][r][ph+2] = ua1.x; sm[buf][0][1][r][ph+2] = ua1.y;
        sm[buf][0][0][r][ph+3] = ua1.z; sm[buf][0][1][r][ph+3] = ua1.w;
        sm[buf][1][0][r][ph+0] = ub0.x; sm[buf][1][1][r][ph+0] = ub0.y;
        sm[buf][1][0][r][ph+1] = ub0.z; sm[buf][1][1][r][ph+1] = ub0.w;
        sm[buf][1][0][r][ph+2] = ub1.x; sm[buf][1][1][r][ph+2] = ub1.y;
        sm[buf][1][0][r][ph+3] = ub1.z; sm[buf][1][1][r][ph+3] = ub1.w;
    };
    auto compute = [&](int buf) {
        uint32_t ah[2][4], al[2][4];
#pragma unroll
        for (int mt = 0; mt < 2; mt++) {
            int m = warpM * 32 + mt * 16 + gid;
            ah[mt][0] = sm[buf][0][0][m][tg];         al[mt][0] = sm[buf][0][1][m][tg];
            ah[mt][1] = sm[buf][0][0][m + 8][tg];     al[mt][1] = sm[buf][0][1][m + 8][tg];
            ah[mt][2] = sm[buf][0][0][m][tg + 4];     al[mt][2] = sm[buf][0][1][m][tg + 4];
            ah[mt][3] = sm[buf][0][0][m + 8][tg + 4]; al[mt][3] = sm[buf][0][1][m + 8][tg + 4];
        }
#pragma unroll
        for (int nt = 0; nt < 8; nt++) {
            int n = warpN * 64 + nt * 8 + gid;
            uint32_t bh0 = sm[buf][1][0][n][tg], bh1 = sm[buf][1][0][n][tg + 4];
            uint32_t bl0 = sm[buf][1][1][n][tg], bl1 = sm[buf][1][1][n][tg + 4];
#pragma unroll
            for (int mt = 0; mt < 2; mt++) {
                mma_bf16(acc[mt][nt], ah[mt], bh0, bh1);
                mma_bf16(acc[mt][nt], ah[mt], bl0, bl1);
                mma_bf16(acc[mt][nt], al[mt], bh0, bh1);
            }
        }
    };

    ldg_slice(0);
    for (int kc = 0; kc < nSlices; kc++) {
        sts_slice(kc & 1);
        if (kc + 1 < nSlices) ldg_slice((kc + 1) * 8);
        __syncthreads();
        compute(kc & 1);
    }

    if (AQ) {
        float p[2][2] = {{0.f, 0.f}, {0.f, 0.f}};
#pragma unroll
        for (int mt = 0; mt < 2; mt++) {
            int r0 = rowBase + warpM * 32 + mt * 16 + gid;
            const float* h0 = hterm + (size_t)(r0 & (BSZ - 1)) * HDIM;
            const float* h1 = hterm + (size_t)((r0 + 8) & (BSZ - 1)) * HDIM;
#pragma unroll
            for (int nt = 0; nt < 8; nt++) {
                int cc = colBase + warpN * 64 + nt * 8 + 2 * tg;
                float w0 = __ldg(Wa2 + cc), w1 = __ldg(Wa2 + cc + 1);
                p[mt][0] += fmaxf(acc[mt][nt][0] + __ldg(h0 + cc), 0.f) * w0
                          + fmaxf(acc[mt][nt][1] + __ldg(h0 + cc + 1), 0.f) * w1;
                p[mt][1] += fmaxf(acc[mt][nt][2] + __ldg(h1 + cc), 0.f) * w0
                          + fmaxf(acc[mt][nt][3] + __ldg(h1 + cc + 1), 0.f) * w1;
            }
        }
#pragma unroll
        for (int mt = 0; mt < 2; mt++)
#pragma unroll
            for (int j = 0; j < 2; j++) {
                p[mt][j] += __shfl_xor_sync(0xffffffffu, p[mt][j], 1);
                p[mt][j] += __shfl_xor_sync(0xffffffffu, p[mt][j], 2);
            }
        if (tg == 0) {
#pragma unroll
            for (int mt = 0; mt < 2; mt++) {
                int r0 = rowBase + warpM * 32 + mt * 16 + gid;
                atomicAdd(&C[r0], p[mt][0]);
                atomicAdd(&C[r0 + 8], p[mt][1]);
            }
        }
    } else {
#pragma unroll
        for (int mt = 0; mt < 2; mt++) {
            int r0 = rowBase + warpM * 32 + mt * 16 + gid;
#pragma unroll
            for (int nt = 0; nt < 8; nt++) {
                int cc = colBase + warpN * 64 + nt * 8 + 2 * tg;
                float b0v = bias ? __ldg(bias + cc) : 0.f;
                float b1v = bias ? __ldg(bias + cc + 1) : 0.f;
                float v0 = acc[mt][nt][0] + b0v, v1 = acc[mt][nt][1] + b1v;
                float v2 = acc[mt][nt][2] + b0v, v3 = acc[mt][nt][3] + b1v;
                if (relu) {
                    v0 = fmaxf(v0, 0.f); v1 = fmaxf(v1, 0.f);
                    v2 = fmaxf(v2, 0.f); v3 = fmaxf(v3, 0.f);
                }
                if (PACKOUT) {
                    uint2* Cp = (uint2*)C;
                    Cp[(size_t)r0 * ldc + (cc >> 1)] = split_pair(v0, v1);
                    Cp[(size_t)(r0 + 8) * ldc + (cc >> 1)] = split_pair(v2, v3);
                } else {
                    *(float2*)&C[(size_t)r0 * ldc + cc] = make_float2(v0, v1);
                    *(float2*)&C[(size_t)(r0 + 8) * ldc + cc] = make_float2(v2, v3);
                }
            }
        }
    }
}

// ---------------------------------------------------------------------------
// pack: fp32 [R, Csrc] (ld lds) -> packed uint2 [R, ldp], zero-pad k >= Csrc
// ---------------------------------------------------------------------------
__global__ void pack_kernel(const float* __restrict__ src, uint2* __restrict__ dst,
                            int R, int Csrc, int lds, int ldp)
{
    int idx = blockIdx.x * blockDim.x + threadIdx.x;
    if (idx >= R * ldp) return;
    int r = idx / ldp, p = idx - r * ldp;
    int k = 2 * p;
    float f0 = (k < Csrc) ? src[(size_t)r * lds + k] : 0.f;
    float f1 = (k + 1 < Csrc) ? src[(size_t)r * lds + k + 1] : 0.f;
    dst[(size_t)r * ldp + p] = split_pair(f0, f1);
}

// warp-dot GEMM: C[m,n] = sum_k A[m,k]*B[n,k]; one warp per output
__global__ void warpdot_kernel(const float* __restrict__ A, const float* __restrict__ B,
                               float* __restrict__ C, int M, int N, int K,
                               int lda, int ldb, int ldc)
{
    int idx = (blockIdx.x * blockDim.x + threadIdx.x) >> 5;
    int lane = threadIdx.x & 31;
    if (idx >= M * N) return;
    int m = idx / N, n = idx - m * N;
    float s = 0.f;
    for (int k = lane; k < K; k += 32) s += A[(size_t)m * lda + k] * B[(size_t)n * ldb + k];
#pragma unroll
    for (int o = 16; o; o >>= 1) s += __shfl_xor_sync(0xffffffffu, s, o);
    if (lane == 0) C[(size_t)m * ldc + n] = s;
}

// vecrow: out[j] = sum_k v[k] * W[j*ldw + k]   (row-dot), one warp per j
__global__ void vecrow_kernel(const float* __restrict__ v, const float* __restrict__ W,
                              float* __restrict__ out, int K, int N, int ldw)
{
    int j = (blockIdx.x * blockDim.x + threadIdx.x) >> 5;
    int lane = threadIdx.x & 31;
    if (j >= N) return;
    float s = 0.f;
    for (int k = lane; k < K; k += 32) s += v[k] * W[(size_t)j * ldw + k];
#pragma unroll
    for (int o = 16; o; o >>= 1) s += __shfl_xor_sync(0xffffffffu, s, o);
    if (lane == 0) out[j] = s;
}

// vecmat: out[j] = sum_k v[k] * W[k*ldw + j] (+bias[j]); one warp per j
__global__ void vecmat_kernel(const float* __restrict__ v, const float* __restrict__ W,
                              const float* __restrict__ bias, float* __restrict__ out,
                              int K, int N, int ldw)
{
    int j = (blockIdx.x * blockDim.x + threadIdx.x) >> 5;
    int lane = threadIdx.x & 31;
    if (j >= N) return;
    float s = 0.f;
    for (int k = lane; k < K; k += 32) s += v[k] * W[(size_t)k * ldw + j];
#pragma unroll
    for (int o = 16; o; o >>= 1) s += __shfl_xor_sync(0xffffffffu, s, o);
    if (lane == 0) out[j] = s + (bias ? bias[j] : 0.f);
}

// bias_gi[n] = b_ih[n] + bov.wih[n,0:256] + bav.wih[n,256:512] + bev.wih[n,512:768]
__global__ void biasgi_kernel(const float* __restrict__ bov, const float* __restrict__ bav,
                              const float* __restrict__ bev, const float* __restrict__ wih,
                              const float* __restrict__ bih, float* __restrict__ out)
{
    int n = (blockIdx.x * blockDim.x + threadIdx.x) >> 5;
    int lane = threadIdx.x & 31;
    if (n >= 3 * HDIM) return;
    float s = 0.f;
    for (int e = lane; e < 768; e += 32) {
        float c = (e < 256) ? bov[e] : (e < 512) ? bav[e - 256] : bev[e - 512];
        s += c * wih[(size_t)n * 768 + e];
    }
#pragma unroll
    for (int o = 16; o; o >>= 1) s += __shfl_xor_sync(0xffffffffu, s, o);
    if (lane == 0) out[n] = s + bih[n];
}

// naive transpose: out[j, i] = in[i, j]  for in[R, C]
__global__ void transpose_kernel(const float* __restrict__ in, float* __restrict__ out,
                                 int R, int C)
{
    int idx = blockIdx.x * blockDim.x + threadIdx.x;
    if (idx >= R * C) return;
    int i = idx / C, j = idx - i * C;
    out[(size_t)j * R + i] = in[idx];
}

// ---------------------------------------------------------------------------
// Attention: one warp per batch element; qproj has row stride ldq.
// ---------------------------------------------------------------------------
template <int D, int Nn>
__global__ void attn_kernel(const float* __restrict__ feats,   // [Nn, B, D]
                            const float* __restrict__ qproj,   // [B, ldq]
                            int ldq, float* __restrict__ fw, int ldf)
{
    constexpr int NC = (D + 31) / 32;
    const int warp = (blockIdx.x * blockDim.x + threadIdx.x) >> 5;
    const int lane = threadIdx.x & 31;
    if (warp >= BSZ) return;
    const int b = warp;

    float qv[NC];
#pragma unroll
    for (int c = 0; c < NC; c++) {
        int d = lane + c * 32;
        qv[c] = (d < D) ? qproj[(size_t)b * ldq + d] : 0.f;
    }

    const float scale = rsqrtf((float)ADIM);
    float myE = 0.f, m = -1e30f;
    for (int n = 0; n < Nn; n++) {
        const float* f = feats + ((size_t)n * BSZ + b) * D;
        float p = 0.f;
#pragma unroll
        for (int c = 0; c < NC; c++) {
            int d = lane + c * 32;
            if (d < D) p += f[d] * qv[c];
        }
#pragma unroll
        for (int o = 16; o; o >>= 1) p += __shfl_xor_sync(0xffffffffu, p, o);
        p *= scale;
        if (lane == n) myE = p;
        m = fmaxf(m, p);
    }
    float wgt = (lane < Nn) ? expf(myE - m) : 0.f;
    float s = wgt;
#pragma unroll
    for (int o = 16; o; o >>= 1) s += __shfl_xor_sync(0xffffffffu, s, o);
    const float attnW = wgt / s;

    float acc[NC];
#pragma unroll
    for (int c = 0; c < NC; c++) acc[c] = 0.f;
    for (int n = 0; n < Nn; n++) {
        float a = __shfl_sync(0xffffffffu, attnW, n);
        const float* f = feats + ((size_t)n * BSZ + b) * D;
#pragma unroll
        for (int c = 0; c < NC; c++) {
            int d = lane + c * 32;
            if (d < D) acc[c] += a * f[d];
        }
    }
#pragma unroll
    for (int c = 0; c < NC; c++) {
        int d = lane + c * 32;
        if (d < D) fw[(size_t)b * ldf + d] = acc[c];
    }
}

// copy own_obs into X[:, 0:128] (X row stride XCOLS)
__global__ void copyx_kernel(const float* __restrict__ own, float* __restrict__ X)
{
    int idx = blockIdx.x * blockDim.x + threadIdx.x;   // over BSZ*32 float4s
    if (idx >= BSZ * 32) return;
    int b = idx >> 5, j4 = idx & 31;
    *(float4*)&X[(size_t)b * XCOLS + j4 * 4] = *(const float4*)&own[(size_t)b * D_OWN + j4 * 4];
}

// GRU gate fusion
__global__ void gru_gate_kernel(const float* __restrict__ gi, const float* __restrict__ gh,
                                const float* __restrict__ hprev, float* __restrict__ hout)
{
    int idx = blockIdx.x * blockDim.x + threadIdx.x;
    if (idx >= BSZ * HDIM) return;
    int b = idx >> 9, k = idx & (HDIM - 1);
    const float* gib = gi + (size_t)b * 3 * HDIM;
    const float* ghb = gh + (size_t)b * 3 * HDIM;
    float ir = gib[k], iz = gib[HDIM + k], in_ = gib[2 * HDIM + k];
    float hr = ghb[k], hz = ghb[HDIM + k], hn  = ghb[2 * HDIM + k];
    float r = 1.f / (1.f + expf(-(ir + hr)));
    float z = 1.f / (1.f + expf(-(iz + hz)));
    float n = tanhf(in_ + r * hn);
    hout[idx] = (1.f - z) * n + z * hprev[idx];
}

// wo_q head
__global__ void woq_kernel(const float* __restrict__ h, const float* __restrict__ Wwo,
                           const float* __restrict__ bwo, float* __restrict__ out)
{
    int idx = blockIdx.x * blockDim.x + threadIdx.x;
    if (idx >= BSZ * NACT) return;
    int b = idx / NACT, j = idx - b * NACT;
    const float* hb = h + (size_t)b * HDIM;
    float s = bwo[j];
#pragma unroll 8
    for (int k = 0; k < HDIM; k++) s += hb[k] * __ldg(&Wwo[k * NACT + j]);
    out[(size_t)b * QOUT + j] = s;
}

// aq finish: out[b, 6+n] = aqpart[n*B + b] + ba2
__global__ void aqfin_kernel(const float* __restrict__ part, const float* __restrict__ ba2,
                             float* __restrict__ out)
{
    int idx = blockIdx.x * blockDim.x + threadIdx.x;
    if (idx >= M_AQ) return;
    int n = idx >> 12, b = idx & (BSZ - 1);
    out[(size_t)b * QOUT + NACT + n] = part[idx] + __ldg(ba2);
}

// ---------------------------------------------------------------------------
// Host launcher
// ---------------------------------------------------------------------------
extern "C" void kernel_launch(void* const* d_in, const int* in_sizes, int n_in,
                              void* d_out, int out_size)
{
    (void)in_sizes; (void)n_in; (void)out_size;
    const float* own_obs = (const float*)d_in[0];
    const float* ally    = (const float*)d_in[1];
    const float* enemy   = (const float*)d_in[2];
    const float* hidden  = (const float*)d_in[3];
    const float* Wq   = (const float*)d_in[4];
    const float* bq   = (const float*)d_in[5];
    const float* Wak  = (const float*)d_in[6];
    const float* Wav  = (const float*)d_in[8];
    const float* bav  = (const float*)d_in[9];
    const float* Wek  = (const float*)d_in[10];
    const float* Wev  = (const float*)d_in[12];
    const float* bev  = (const float*)d_in[13];
    const float* Wov  = (const float*)d_in[14];
    const float* bov  = (const float*)d_in[15];
    const float* w_ih = (const float*)d_in[16];
    const float* w_hh = (const float*)d_in[17];
    const float* b_ih = (const float*)d_in[18];
    const float* b_hh = (const float*)d_in[19];
    const float* Wwo  = (const float*)d_in[20];
    const float* bwo  = (const float*)d_in[21];
    const float* We1  = (const float*)d_in[22];
    const float* be1  = (const float*)d_in[23];
    const float* We2  = (const float*)d_in[24];
    const float* be2  = (const float*)d_in[25];
    const float* Wa1  = (const float*)d_in[26];
    const float* ba1  = (const float*)d_in[27];
    const float* Wa2  = (const float*)d_in[28];
    const float* ba2  = (const float*)d_in[29];

    float* out   = (float*)d_out;
    float* h_out = out + (size_t)BSZ * QOUT;

    float *p_X, *p_qaqe, *p_gi, *p_gh, *p_hterm, *p_cvec, *p_We1T;
    float *p_Wa1topT, *p_Wa1botT, *p_Bq, *p_bqaqe, *p_biasgi, *p_aqpart;
    uint2 *p_Ep, *p_We1Tp, *p_We2p, *p_Wa1topTp, *p_Mtp, *p_Wa1botTp;
    uint2 *p_wihp, *p_Wovp, *p_Wavp, *p_Wevp, *p_Wgip, *p_whhp;
    uint2 *p_Bqp, *p_ownp, *p_Xp, *p_hidp, *p_hp, *p_relu1p;
    cudaGetSymbolAddress((void**)&p_X, g_X);
    cudaGetSymbolAddress((void**)&p_qaqe, g_qaqe);
    cudaGetSymbolAddress((void**)&p_gi, g_gi);
    cudaGetSymbolAddress((void**)&p_gh, g_gh);
    cudaGetSymbolAddress((void**)&p_hterm, g_hterm);
    cudaGetSymbolAddress((void**)&p_cvec, g_cvec);
    cudaGetSymbolAddress((void**)&p_We1T, g_We1T);
    cudaGetSymbolAddress((void**)&p_Wa1topT, g_Wa1topT);
    cudaGetSymbolAddress((void**)&p_Wa1botT, g_Wa1botT);
    cudaGetSymbolAddress((void**)&p_Bq, g_Bq);
    cudaGetSymbolAddress((void**)&p_bqaqe, g_bqaqe);
    cudaGetSymbolAddress((void**)&p_biasgi, g_biasgi);
    cudaGetSymbolAddress((void**)&p_aqpart, g_aqpart);
    cudaGetSymbolAddress((void**)&p_Ep, g_Ep);
    cudaGetSymbolAddress((void**)&p_We1Tp, g_We1Tp);
    cudaGetSymbolAddress((void**)&p_We2p, g_We2p);
    cudaGetSymbolAddress((void**)&p_Wa1topTp, g_Wa1topTp);
    cudaGetSymbolAddress((void**)&p_Mtp, g_Mtp);
    cudaGetSymbolAddress((void**)&p_Wa1botTp, g_Wa1botTp);
    cudaGetSymbolAddress((void**)&p_wihp, g_wihp);
    cudaGetSymbolAddress((void**)&p_Wovp, g_Wovp);
    cudaGetSymbolAddress((void**)&p_Wavp, g_Wavp);
    cudaGetSymbolAddress((void**)&p_Wevp, g_Wevp);
    cudaGetSymbolAddress((void**)&p_Wgip, g_Wgip);
    cudaGetSymbolAddress((void**)&p_whhp, g_whhp);
    cudaGetSymbolAddress((void**)&p_Bqp, g_Bqp);
    cudaGetSymbolAddress((void**)&p_ownp, g_ownp);
    cudaGetSymbolAddress((void**)&p_Xp, g_Xp);
    cudaGetSymbolAddress((void**)&p_hidp, g_hidp);
    cudaGetSymbolAddress((void**)&p_hp, g_hp);
    cudaGetSymbolAddress((void**)&p_relu1p, g_relu1p);

    const int T = 256;
    auto blks = [](long n) { return (int)((n + 255) / 256); };

    // ---- prep: relu1 dependencies first ----
    pack_kernel<<<blks((long)M_AQ * KP_E), T>>>(enemy, p_Ep, M_AQ, D_EN, D_EN, KP_E);
    transpose_kernel<<<blks(65 * 512), T>>>(We1, p_We1T, 65, 512);
    pack_kernel<<<blks(512 * KP_E), T>>>(p_We1T, p_We1Tp, 512, D_EN, D_EN, KP_E);
    // relu1 = relu(E @ We1 + be1), packed out
    mma_pk<0, 1><<<dim3(4, 1024), 256>>>(p_Ep, p_We1Tp, be1, (float*)p_relu1p,
                                         nullptr, nullptr, KP_E, KP_E, KP_E, KP_H, 1);

    // ---- Mt (packed, tensor-core): Mt[j,i] = sum_k Wa1topT[j,k]*We2[i,k] ----
    transpose_kernel<<<blks(512 * 512), T>>>(Wa1, p_Wa1topT, 512, 512);
    pack_kernel<<<blks(512 * KP_H), T>>>(p_Wa1topT, p_Wa1topTp, 512, 512, 512, KP_H);
    pack_kernel<<<blks(512 * KP_H), T>>>(We2, p_We2p, 512, 512, 512, KP_H);
    mma_pk<0, 1><<<dim3(4, 4), 256>>>(p_Wa1topTp, p_We2p, nullptr, (float*)p_Mtp,
                                      nullptr, nullptr, KP_H, KP_H, KP_H, KP_H, 0);

    // ---- Wa1bot ----
    transpose_kernel<<<blks(512 * 512), T>>>(Wa1 + (size_t)HDIM * HDIM, p_Wa1botT, 512, 512);
    pack_kernel<<<blks(512 * KP_H), T>>>(p_Wa1botT, p_Wa1botTp, 512, 512, 512, KP_H);

    // ---- Wgi folds (tensor-core, packed-out into Wgip segments) ----
    pack_kernel<<<blks((long)1536 * 128), T>>>(w_ih,       p_wihp,              1536, 256, 768, 128);
    pack_kernel<<<blks((long)1536 * 128), T>>>(w_ih + 256, p_wihp + 1536*128,   1536, 256, 768, 128);
    pack_kernel<<<blks((long)1536 * 128), T>>>(w_ih + 512, p_wihp + 2*1536*128, 1536, 256, 768, 128);
    pack_kernel<<<blks(128 * 128), T>>>(Wov, p_Wovp, 128, 256, 256, 128);
    cudaMemsetAsync(p_Wavp, 0, 128 * 128 * sizeof(uint2), 0);
    cudaMemsetAsync(p_Wevp, 0, 128 * 128 * sizeof(uint2), 0);
    pack_kernel<<<blks(64 * 128), T>>>(Wav, p_Wavp, 64, 256, 256, 128);
    pack_kernel<<<blks(65 * 128), T>>>(Wev, p_Wevp, 65, 256, 256, 128);
    mma_pk<0, 1><<<dim3(1, 12), 256>>>(p_wihp,              p_Wovp, nullptr, (float*)p_Wgip,
                                       nullptr, nullptr, 128, 128, 128, KP_X, 0);
    mma_pk<0, 1><<<dim3(1, 12), 256>>>(p_wihp + 1536*128,   p_Wavp, nullptr, (float*)(p_Wgip + 64),
                                       nullptr, nullptr, 128, 128, 128, KP_X, 0);
    mma_pk<0, 1><<<dim3(1, 12), 256>>>(p_wihp + 2*1536*128, p_Wevp, nullptr, (float*)(p_Wgip + 128),
                                       nullptr, nullptr, 128, 128, 128, KP_X, 0);
    biasgi_kernel<<<blks(1536 * 32), T>>>(bov, bav, bev, w_ih, b_ih, p_biasgi);

    // ---- folded query head ----
    cudaMemsetAsync(p_Bq, 0, 256 * ADIM * sizeof(float), 0);
    cudaMemsetAsync(p_bqaqe, 0, 256 * sizeof(float), 0);
    warpdot_kernel<<<blks((long)64 * 128 * 32), T>>>(Wak, Wq, p_Bq, 64, 128, 128, 128, 128, 128);
    warpdot_kernel<<<blks((long)65 * 128 * 32), T>>>(Wek, Wq, p_Bq + 64 * 128, 65, 128, 128, 128, 128, 128);
    vecrow_kernel<<<blks(64 * 32), T>>>(bq, Wak, p_bqaqe, 128, 64, 128);
    vecrow_kernel<<<blks(65 * 32), T>>>(bq, Wek, p_bqaqe + 64, 128, 65, 128);
    pack_kernel<<<blks(256 * 64), T>>>(p_Bq, p_Bqp, 256, 128, 128, 64);

    vecmat_kernel<<<blks(512 * 32), T>>>(be2, Wa1, ba1, p_cvec, 512, 512, 512);
    pack_kernel<<<blks((long)1536 * KP_H), T>>>(w_hh, p_whhp, 1536, 512, 512, KP_H);

    // ---- batch path ----
    pack_kernel<<<blks((long)BSZ * 64), T>>>(own_obs, p_ownp, BSZ, 128, 128, 64);
    mma_pk<0, 0><<<dim3(2, 32), 256>>>(p_ownp, p_Bqp, p_bqaqe, p_qaqe,
                                       nullptr, nullptr, 64, 64, 64, 256, 0);
    cudaMemsetAsync(p_X, 0, (size_t)BSZ * XCOLS * sizeof(float), 0);
    copyx_kernel<<<blks(BSZ * 32), T>>>(own_obs, p_X);
    attn_kernel<D_AL, NALLY><<<BSZ / 8, T>>>(ally, p_qaqe, 256, p_X + 128, XCOLS);
    attn_kernel<D_EN, NEN><<<BSZ / 8, T>>>(enemy, p_qaqe + 64, 256, p_X + 256, XCOLS);
    pack_kernel<<<blks((long)BSZ * KP_X), T>>>(p_X, p_Xp, BSZ, XCOLS, XCOLS, KP_X);
    pack_kernel<<<blks((long)BSZ * KP_H), T>>>(hidden, p_hidp, BSZ, 512, 512, KP_H);

    // GRU
    mma_pk<0, 0><<<dim3(12, 32), 256>>>(p_Xp, p_Wgip, p_biasgi, p_gi,
                                        nullptr, nullptr, KP_X, KP_X, KP_X, 3 * HDIM, 0);
    mma_pk<0, 0><<<dim3(12, 32), 256>>>(p_hidp, p_whhp, b_hh, p_gh,
                                        nullptr, nullptr, KP_H, KP_H, KP_H, 3 * HDIM, 0);
    gru_gate_kernel<<<blks(BSZ * HDIM), T>>>(p_gi, p_gh, hidden, h_out);
    pack_kernel<<<blks((long)BSZ * KP_H), T>>>(h_out, p_hp, BSZ, 512, 512, KP_H);

    // heads
    woq_kernel<<<blks(BSZ * NACT), T>>>(h_out, Wwo, bwo, out);
    mma_pk<0, 0><<<dim3(4, 32), 256>>>(p_hp, p_Wa1botTp, p_cvec, p_hterm,
                                       nullptr, nullptr, KP_H, KP_H, KP_H, HDIM, 0);
    cudaMemsetAsync(p_aqpart, 0, (size_t)M_AQ * sizeof(float), 0);
    mma_pk<1, 0><<<dim3(4, 1024), 256>>>(p_relu1p, p_Mtp, nullptr, p_aqpart,
                                         p_hterm, Wa2, KP_H, KP_H, KP_H, 0, 0);
    aqfin_kernel<<<blks(M_AQ), T>>>(p_aqpart, ba2, out);
}